// round 4
// baseline (speedup 1.0000x reference)
#include <cuda_runtime.h>

namespace {

constexpr int RAD  = 7;         // N = 2*ceil(2.5)+1 = 7
constexpr int TBX  = 32;        // output tile width  (threads x)
constexpr int TBY  = 8;         // output tile height (threads y)
constexpr int SW   = TBX + 2*RAD; // 46 smem tile width
constexpr int SH   = TBY + 2*RAD; // 22 smem tile height
constexpr int IMH  = 1080;
constexpr int IMW  = 1920;
constexpr int CH   = 11;

#define EPSF    1e-4f
#define LOG2E_F 1.4426950408889634f
#define NHALF_LOG2E_F 0.7213475204444817f   /* 0.5*log2(e) */

__device__ __forceinline__ float ex2f_(float x) {
    float y;
    asm("ex2.approx.f32 %0, %1;" : "=f"(y) : "f"(x));
    return y;
}

} // namespace

__global__ void __launch_bounds__(TBX*TBY)
BilateralDenoiser_44427141710593_kernel(const float* __restrict__ in,
                                        float* __restrict__ out)
{
    __shared__ float4 s_nz[SH * SW];   // (nrm.x, nrm.y, nrm.z, z)
    __shared__ float4 s_cd[SH * SW];   // (col.r, col.g, col.b, dz)

    const int bx  = blockIdx.x * TBX;
    const int by  = blockIdx.y * TBY;
    const int tid = threadIdx.y * TBX + threadIdx.x;

    // Cooperative halo load; out-of-bounds -> zeros, which makes
    // dot = 0 -> clip(eps)^128 underflows to exactly 0 -> w = 0 (matches the
    // reference, which also underflows 1e-4^128 to 0 in fp32).
    #pragma unroll
    for (int i = tid; i < SH * SW; i += TBX * TBY) {
        const int ly = i / SW;
        const int lx = i - ly * SW;
        const int gy = by + ly - RAD;
        const int gx = bx + lx - RAD;
        float4 nz = make_float4(0.f, 0.f, 0.f, 0.f);
        float4 cd = make_float4(0.f, 0.f, 0.f, 0.f);
        if ((unsigned)gy < (unsigned)IMH && (unsigned)gx < (unsigned)IMW) {
            const float* p = in + ((size_t)gy * IMW + gx) * CH;
            cd.x = p[0]; cd.y = p[1]; cd.z = p[2];      // col
            nz.x = p[3]; nz.y = p[4]; nz.z = p[5];      // nrm
            nz.w = p[9];                                 // z
            cd.w = p[10];                                // dz
        }
        s_nz[i] = nz;
        s_cd[i] = cd;
    }
    __syncthreads();

    const int c = (threadIdx.y + RAD) * SW + (threadIdx.x + RAD);
    const float4* __restrict__ snz = s_nz + c;
    const float4* __restrict__ scd = s_cd + c;

    const float4 cnz = snz[0];
    const float  Nx = cnz.x, Ny = cnz.y, Nz = cnz.z, Zc = cnz.w;
    const float  dzc = scd[0].w;

    float ar = 0.f, ag = 0.f, ab = 0.f, aw = 0.f;

    #pragma unroll
    for (int dy = -RAD; dy <= RAD; ++dy) {
        #pragma unroll
        for (int dx = -RAD; dx <= RAD; ++dx) {
            const float dsi  = (float)(dy*dy + dx*dx);     // loop-constant
            const float dist = sqrtf(dsi);                 // folded after unroll
            const float ctap = -NHALF_LOG2E_F * dsi;       // -0.5*d^2*log2e

            const float4 nz = snz[dy*SW + dx];
            const float4 cd = scd[dy*SW + dx];

            float dot = nz.x*Nx + nz.y*Ny + nz.z*Nz;
            float t = fminf(fmaxf(dot, EPSF), 1.0f);
            t = t*t; t = t*t; t = t*t; t = t*t; t = t*t; t = t*t; t = t*t; // ^128

            float den = fmaxf(dzc * dist, EPSF);
            float zd  = fabsf(nz.w - Zc);
            float r   = __fdividef(zd, den);

            float w = ex2f_(fmaf(r, -LOG2E_F, ctap)) * t;

            ar = fmaf(cd.x, w, ar);
            ag = fmaf(cd.y, w, ag);
            ab = fmaf(cd.z, w, ab);
            aw += w;
        }
    }

    const float inv = 1.0f / fmaxf(aw, EPSF);
    const int gy = by + threadIdx.y;
    const int gx = bx + threadIdx.x;
    float* o = out + ((size_t)gy * IMW + gx) * 3;
    o[0] = ar * inv;
    o[1] = ag * inv;
    o[2] = ab * inv;
}

extern "C" void kernel_launch(void* const* d_in, const int* in_sizes, int n_in,
                              void* d_out, int out_size)
{
    const float* in = (const float*)d_in[0];
    float* out = (float*)d_out;
    dim3 block(TBX, TBY);
    dim3 grid(IMW / TBX, IMH / TBY);   // 60 x 135, exact tiling
    BilateralDenoiser_44427141710593_kernel<<<grid, block>>>(in, out);
}

// round 5
// speedup vs baseline: 1.0049x; 1.0049x over previous
#include <cuda_runtime.h>

namespace {

constexpr int RAD  = 7;         // N = 2*ceil(2.5)+1 = 7
constexpr int TBX  = 32;        // output tile width  (threads x)
constexpr int TBY  = 8;         // output tile height (threads y)
constexpr int SW   = TBX + 2*RAD; // 46 smem tile width
constexpr int SH   = TBY + 2*RAD; // 22 smem tile height
constexpr int IMH  = 1080;
constexpr int IMW  = 1920;
constexpr int CH   = 11;

#define EPSF    1e-4f
#define LOG2E_F 1.4426950408889634f
#define NHALF_LOG2E_F 0.7213475204444817f   /* 0.5*log2(e) */

__device__ __forceinline__ float ex2f_(float x) {
    float y;
    asm("ex2.approx.f32 %0, %1;" : "=f"(y) : "f"(x));
    return y;
}

} // namespace

__global__ void __launch_bounds__(TBX*TBY)
BilateralDenoiser_44427141710593_kernel(const float* __restrict__ in,
                                        float* __restrict__ out)
{
    __shared__ float4 s_nz[SH * SW];   // (nrm.x, nrm.y, nrm.z, z)
    __shared__ float4 s_cd[SH * SW];   // (col.r, col.g, col.b, dz)

    const int bx  = blockIdx.x * TBX;
    const int by  = blockIdx.y * TBY;
    const int tid = threadIdx.y * TBX + threadIdx.x;

    // Cooperative halo load; out-of-bounds -> zeros, which makes
    // dot = 0 -> clip(eps)^128 underflows to exactly 0 -> w = 0 (matches the
    // reference, which also underflows 1e-4^128 to 0 in fp32).
    #pragma unroll
    for (int i = tid; i < SH * SW; i += TBX * TBY) {
        const int ly = i / SW;
        const int lx = i - ly * SW;
        const int gy = by + ly - RAD;
        const int gx = bx + lx - RAD;
        float4 nz = make_float4(0.f, 0.f, 0.f, 0.f);
        float4 cd = make_float4(0.f, 0.f, 0.f, 0.f);
        if ((unsigned)gy < (unsigned)IMH && (unsigned)gx < (unsigned)IMW) {
            const float* p = in + ((size_t)gy * IMW + gx) * CH;
            cd.x = p[0]; cd.y = p[1]; cd.z = p[2];      // col
            nz.x = p[3]; nz.y = p[4]; nz.z = p[5];      // nrm
            nz.w = p[9];                                 // z
            cd.w = p[10];                                // dz
        }
        s_nz[i] = nz;
        s_cd[i] = cd;
    }
    __syncthreads();

    const int c = (threadIdx.y + RAD) * SW + (threadIdx.x + RAD);
    const float4* __restrict__ snz = s_nz + c;
    const float4* __restrict__ scd = s_cd + c;

    const float4 cnz = snz[0];
    const float  Nx = cnz.x, Ny = cnz.y, Nz = cnz.z, Zc = cnz.w;
    const float  dzc = scd[0].w;

    float ar = 0.f, ag = 0.f, ab = 0.f, aw = 0.f;

    #pragma unroll
    for (int dy = -RAD; dy <= RAD; ++dy) {
        #pragma unroll
        for (int dx = -RAD; dx <= RAD; ++dx) {
            const float dsi  = (float)(dy*dy + dx*dx);     // loop-constant
            const float dist = sqrtf(dsi);                 // folded after unroll
            const float ctap = -NHALF_LOG2E_F * dsi;       // -0.5*d^2*log2e

            const float4 nz = snz[dy*SW + dx];
            const float4 cd = scd[dy*SW + dx];

            float dot = nz.x*Nx + nz.y*Ny + nz.z*Nz;
            float t = fminf(fmaxf(dot, EPSF), 1.0f);
            t = t*t; t = t*t; t = t*t; t = t*t; t = t*t; t = t*t; t = t*t; // ^128

            float den = fmaxf(dzc * dist, EPSF);
            float zd  = fabsf(nz.w - Zc);
            float r   = __fdividef(zd, den);

            float w = ex2f_(fmaf(r, -LOG2E_F, ctap)) * t;

            ar = fmaf(cd.x, w, ar);
            ag = fmaf(cd.y, w, ag);
            ab = fmaf(cd.z, w, ab);
            aw += w;
        }
    }

    const float inv = 1.0f / fmaxf(aw, EPSF);
    const int gy = by + threadIdx.y;
    const int gx = bx + threadIdx.x;
    float* o = out + ((size_t)gy * IMW + gx) * 3;
    o[0] = ar * inv;
    o[1] = ag * inv;
    o[2] = ab * inv;
}

extern "C" void kernel_launch(void* const* d_in, const int* in_sizes, int n_in,
                              void* d_out, int out_size)
{
    const float* in = (const float*)d_in[0];
    float* out = (float*)d_out;
    dim3 block(TBX, TBY);
    dim3 grid(IMW / TBX, IMH / TBY);   // 60 x 135, exact tiling
    BilateralDenoiser_44427141710593_kernel<<<grid, block>>>(in, out);
}